// round 13
// baseline (speedup 1.0000x reference)
#include <cuda_runtime.h>
#include <cstdint>

#define NN 50000
#define NE 800000
#define D  128
#define EPSV 1e-5f
#define NBLK 196   // ceil(NN/256)

// ---------------- scratch ----------------
__device__ float g_s[(size_t)NN * D];      // aggregated (mean) features
__device__ float g_hp[(size_t)NN * D];     // pre-norm GEMM output
__device__ float g_xres[(size_t)NN * D];   // x @ Wres^T
__device__ float g_stats[2 * D];
__device__ float g_np[3 * D];              // a*mean | w*rsqrt(var+eps) | b
__device__ int   g_icnt[NN];
__device__ int   g_rowptr[NN + 1];
__device__ int   g_fill[NN];
__device__ int   g_adj[NE];
__device__ int   g_bsum[NBLK];
__device__ int   g_boff[NBLK];
__device__ float g_Wc1[256 * 128];         // [n][k] tf32-rounded concat [Wl1|Wr1]
__device__ float g_Wc2[256 * 128];
__device__ float g_Wrt[128 * 128];         // [n][k] tf32-rounded Wres

// ---------------- tf32 helpers ----------------
__device__ __forceinline__ uint32_t f2tf32(float f) {
    uint32_t r;
    asm("cvt.rna.tf32.f32 %0, %1;" : "=r"(r) : "f"(f));
    return r;
}
__device__ __forceinline__ void mma_tf32(float* d, const uint32_t* a,
                                         uint32_t b0, uint32_t b1) {
    asm volatile(
        "mma.sync.aligned.m16n8k8.row.col.f32.tf32.tf32.f32 "
        "{%0,%1,%2,%3}, {%4,%5,%6,%7}, {%8,%9}, {%0,%1,%2,%3};"
        : "+f"(d[0]), "+f"(d[1]), "+f"(d[2]), "+f"(d[3])
        : "r"(a[0]), "r"(a[1]), "r"(a[2]), "r"(a[3]), "r"(b0), "r"(b1));
}
__device__ __forceinline__ uint32_t smem_u32(const void* p) {
    uint32_t a;
    asm("{ .reg .u64 t; cvta.to.shared.u64 t, %1; cvt.u32.u64 %0, t; }" : "=r"(a) : "l"(p));
    return a;
}
__device__ __forceinline__ void cp16(uint32_t dst, const void* src) {
    asm volatile("cp.async.cg.shared.global [%0], [%1], 16;" :: "r"(dst), "l"(src));
}
__device__ __forceinline__ void cp16z(uint32_t dst, const void* src, int sz) {
    asm volatile("cp.async.cg.shared.global [%0], [%1], 16, %2;"
                 :: "r"(dst), "l"(src), "r"(sz));
}

// ---------------- weight pre-conversion (tf32 round, concat layout) ----------
__global__ void prep_w(const float* __restrict__ Wl1, const float* __restrict__ Wr1,
                       const float* __restrict__ Wl2, const float* __restrict__ Wr2,
                       const float* __restrict__ Wres)
{
    int idx = blockIdx.x * blockDim.x + threadIdx.x;
    if (idx < 128 * 256) {
        int n = idx >> 8, k = idx & 255;
        float v1 = (k < D) ? Wl1[n * D + k] : Wr1[n * D + (k - D)];
        float v2 = (k < D) ? Wl2[n * D + k] : Wr2[n * D + (k - D)];
        g_Wc1[idx] = __uint_as_float(f2tf32(v1));
        g_Wc2[idx] = __uint_as_float(f2tf32(v2));
    } else if (idx < 128 * 256 + 128 * 128) {
        int t = idx - 128 * 256;
        g_Wrt[t] = __uint_as_float(f2tf32(Wres[t]));
    }
}

// ---------------- small zero (counters + stats) ----------------
__global__ void zero_kernel()
{
    int idx = blockIdx.x * blockDim.x + threadIdx.x;
    if (idx < NN) g_icnt[idx] = 0;
    if (idx < 2 * D) g_stats[idx] = 0.f;
}

// ---------------- CSR build (vectorized int4 edge reads) ----------------
__global__ void count_kernel(const int* __restrict__ ei)
{
    int q = blockIdx.x * blockDim.x + threadIdx.x;   // quad index
    if (q >= NE / 4) return;
    int4 d4 = __ldg(reinterpret_cast<const int4*>(ei + NE) + q);
    if ((unsigned)d4.x < NN) atomicAdd(&g_icnt[d4.x], 1);
    if ((unsigned)d4.y < NN) atomicAdd(&g_icnt[d4.y], 1);
    if ((unsigned)d4.z < NN) atomicAdd(&g_icnt[d4.z], 1);
    if ((unsigned)d4.w < NN) atomicAdd(&g_icnt[d4.w], 1);
}

__global__ void bsum_kernel()
{
    __shared__ int sh[256];
    int t = threadIdx.x;
    int i = blockIdx.x * 256 + t;
    int v = (i < NN) ? g_icnt[i] : 0;
    sh[t] = v;
    __syncthreads();
    for (int off = 128; off > 0; off >>= 1) {
        if (t < off) sh[t] += sh[t + off];
        __syncthreads();
    }
    if (t == 0) g_bsum[blockIdx.x] = sh[0];
}

__global__ void bscan_kernel()
{
    __shared__ int sh[256];
    int t = threadIdx.x;
    int v = (t < NBLK) ? g_bsum[t] : 0;
    sh[t] = v;
    __syncthreads();
#pragma unroll
    for (int off = 1; off < 256; off <<= 1) {
        int u = (t >= off) ? sh[t - off] : 0;
        __syncthreads();
        sh[t] += u;
        __syncthreads();
    }
    if (t < NBLK) g_boff[t] = sh[t] - v;   // exclusive
}

__global__ void rowptr_kernel()
{
    __shared__ int sh[256];
    int t = threadIdx.x;
    int i = blockIdx.x * 256 + t;
    int v = (i < NN) ? g_icnt[i] : 0;
    sh[t] = v;
    __syncthreads();
#pragma unroll
    for (int off = 1; off < 256; off <<= 1) {
        int u = (t >= off) ? sh[t - off] : 0;
        __syncthreads();
        sh[t] += u;
        __syncthreads();
    }
    if (i < NN) {
        int ex = g_boff[blockIdx.x] + sh[t] - v;
        g_rowptr[i] = ex;
        g_fill[i] = ex;
        if (i == NN - 1) g_rowptr[NN] = ex + v;
    }
}

__global__ void fill_kernel(const int* __restrict__ ei)
{
    int q = blockIdx.x * blockDim.x + threadIdx.x;
    if (q >= NE / 4) return;
    int4 s4 = __ldg(reinterpret_cast<const int4*>(ei) + q);
    int4 d4 = __ldg(reinterpret_cast<const int4*>(ei + NE) + q);
    if ((unsigned)s4.x < NN && (unsigned)d4.x < NN) g_adj[atomicAdd(&g_fill[d4.x], 1)] = s4.x;
    if ((unsigned)s4.y < NN && (unsigned)d4.y < NN) g_adj[atomicAdd(&g_fill[d4.y], 1)] = s4.y;
    if ((unsigned)s4.z < NN && (unsigned)d4.z < NN) g_adj[atomicAdd(&g_fill[d4.z], 1)] = s4.z;
    if ((unsigned)s4.w < NN && (unsigned)d4.w < NN) g_adj[atomicAdd(&g_fill[d4.w], 1)] = s4.w;
}

// ---------------- CSR gather (mean aggregate); NORM applies graphnorm+relu ----
template <bool NORM>
__global__ void gather_kernel(const float* __restrict__ src)
{
    int w = (blockIdx.x * blockDim.x + threadIdx.x) >> 5;
    int lane = threadIdx.x & 31;
    if (w >= NN) return;
    int beg = g_rowptr[w];
    int end = g_rowptr[w + 1];
    float4 nm, nw, nb;
    if (NORM) {
        nm = __ldg(reinterpret_cast<const float4*>(g_np) + lane);
        nw = __ldg(reinterpret_cast<const float4*>(g_np + D) + lane);
        nb = __ldg(reinterpret_cast<const float4*>(g_np + 2 * D) + lane);
    }
    float4 acc = make_float4(0.f, 0.f, 0.f, 0.f);
#pragma unroll 4
    for (int j = beg; j < end; j++) {
        int s = __ldg(g_adj + j);
        float4 v = __ldg(reinterpret_cast<const float4*>(src + (size_t)s * D) + lane);
        if (NORM) {
            v.x = fmaxf(nw.x * (v.x - nm.x) + nb.x, 0.f);
            v.y = fmaxf(nw.y * (v.y - nm.y) + nb.y, 0.f);
            v.z = fmaxf(nw.z * (v.z - nm.z) + nb.z, 0.f);
            v.w = fmaxf(nw.w * (v.w - nm.w) + nb.w, 0.f);
        }
        acc.x += v.x; acc.y += v.y; acc.z += v.z; acc.w += v.w;
    }
    float inv = 1.0f / fmaxf((float)(end - beg), 1.0f);
    acc.x *= inv; acc.y *= inv; acc.z *= inv; acc.w *= inv;
    reinterpret_cast<float4*>(g_s + (size_t)w * D)[lane] = acc;
}

// ---------------- mma.sync tf32 GEMM ----------------
// out[NN,128] = [A0 | normA1?(A1)] @ Wt^T (+bias); Wt pre-converted tf32 [n][KS]
// k-slot permutation: hw slot tg <-> logical k=kb+2tg, slot tg+4 <-> kb+2tg+1
// (valid: contraction over k is permutation-invariant; applied to A AND B)
#define KP 36
#define BUFF (128 * KP)

template <int KC, bool CONCAT, bool STATS, bool NORMA1>
__global__ __launch_bounds__(256, 2)
void gemm_mma(const float* __restrict__ A0, const float* __restrict__ A1,
              const float* __restrict__ Wt,
              const float* __restrict__ bias, float* __restrict__ out)
{
    constexpr int KS = KC * 32;
    extern __shared__ float sm[];
    float* As  = sm;                 // [2][128][KP]
    float* Bs  = sm + 2 * BUFF;      // [2][128][KP]
    float* npS = sm + 4 * BUFF;      // [384]
    float* sumS = sm;                // stats scratch (reuse As after compute)
    float* sqS  = sm + 512;

    const uint32_t sA = smem_u32(As);
    const uint32_t sB = smem_u32(Bs);
    const int tid = threadIdx.x;
    const int wid = tid >> 5, lane = tid & 31;
    const int warpM = wid >> 1;
    const int warpN = wid & 1;
    const int gid = lane >> 2;
    const int tg  = lane & 3;
    const int rowBase = blockIdx.x * 128;

    if (NORMA1) {
        for (int i = tid; i < 3 * D; i += 256) npS[i] = g_np[i];
    }

    float acc[2][8][4];
#pragma unroll
    for (int m = 0; m < 2; m++)
#pragma unroll
        for (int n = 0; n < 8; n++)
#pragma unroll
            for (int q = 0; q < 4; q++) acc[m][n][q] = 0.f;

    auto issueChunk = [&](int kc, int buf) {
#pragma unroll
        for (int i = 0; i < 4; i++) {
            int f = tid + i * 256;
            int r = f >> 3;
            int kg = f & 7;
            int k = kc * 32 + kg * 4;
            uint32_t soff = (uint32_t)(buf * BUFF + r * KP + kg * 4) * 4u;
            int rg = rowBase + r;
            const float* gp;
            if (CONCAT && k >= D) gp = A1 + (size_t)rg * D + (k - D);
            else                  gp = A0 + (size_t)rg * D + k;
            int sz = 16;
            if (rg >= NN) { gp = A0; sz = 0; }
            cp16z(sA + soff, gp, sz);
            cp16(sB + soff, Wt + r * KS + k);
        }
        asm volatile("cp.async.commit_group;" ::: "memory");
    };

    issueChunk(0, 0);

#pragma unroll
    for (int kc = 0; kc < KC; kc++) {
        if (kc + 1 < KC) {
            issueChunk(kc + 1, (kc + 1) & 1);
            asm volatile("cp.async.wait_group 1;" ::: "memory");
        } else {
            asm volatile("cp.async.wait_group 0;" ::: "memory");
        }
        __syncthreads();

        const int buf = kc & 1;
        const float* ab = &As[buf * BUFF];
        const float* bb = &Bs[buf * BUFF];
        const bool isA1 = CONCAT && (kc >= 4);

#pragma unroll
        for (int ks = 0; ks < 4; ks++) {
            const int kb = ks * 8;
            const int kp = kb + 2 * tg;          // logical k pair base (permuted)
            float nm0 = 0.f, nw0 = 1.f, nb0 = 0.f, nm1 = 0.f, nw1 = 1.f, nb1 = 0.f;
            if (NORMA1 && isA1) {
                int c0 = (kc - 4) * 32 + kp;     // slot tg  -> logical col c0
                int c1 = c0 + 1;                 // slot tg+4 -> logical col c0+1
                nm0 = npS[c0]; nw0 = npS[D + c0]; nb0 = npS[2 * D + c0];
                nm1 = npS[c1]; nw1 = npS[D + c1]; nb1 = npS[2 * D + c1];
            }
            uint32_t a[2][4];
#pragma unroll
            for (int m = 0; m < 2; m++) {
                int r1 = warpM * 32 + m * 16 + gid;
                int r2 = r1 + 8;
                float2 p1 = *reinterpret_cast<const float2*>(&ab[r1 * KP + kp]);
                float2 p2 = *reinterpret_cast<const float2*>(&ab[r2 * KP + kp]);
                float v0 = p1.x, v2 = p1.y;      // slots tg, tg+4 for row r1
                float v1 = p2.x, v3 = p2.y;      // slots tg, tg+4 for row r2
                if (NORMA1 && isA1) {
                    v0 = fmaxf(nw0 * (v0 - nm0) + nb0, 0.f);
                    v1 = fmaxf(nw0 * (v1 - nm0) + nb0, 0.f);
                    v2 = fmaxf(nw1 * (v2 - nm1) + nb1, 0.f);
                    v3 = fmaxf(nw1 * (v3 - nm1) + nb1, 0.f);
                }
                a[m][0] = f2tf32(v0); a[m][1] = f2tf32(v1);
                a[m][2] = f2tf32(v2); a[m][3] = f2tf32(v3);
            }
#pragma unroll
            for (int n = 0; n < 8; n++) {
                int c = warpN * 64 + n * 8 + gid;
                float2 pb = *reinterpret_cast<const float2*>(&bb[c * KP + kp]);
                uint32_t b0 = __float_as_uint(pb.x);   // pre-tf32
                uint32_t b1 = __float_as_uint(pb.y);
                mma_tf32(acc[0][n], a[0], b0, b1);
                mma_tf32(acc[1][n], a[1], b0, b1);
            }
        }
        __syncthreads();
    }

    // ---- epilogue: bias + store + (stats) ----
    const bool hasBias = (bias != nullptr);
    bool valid[2][2];
#pragma unroll
    for (int m = 0; m < 2; m++)
#pragma unroll
        for (int h = 0; h < 2; h++)
            valid[m][h] = (rowBase + warpM * 32 + m * 16 + h * 8 + gid) < NN;

#pragma unroll
    for (int n = 0; n < 8; n++) {
        int col = warpN * 64 + n * 8 + tg * 2;
        float b0 = hasBias ? __ldg(bias + col) : 0.f;
        float b1 = hasBias ? __ldg(bias + col + 1) : 0.f;
        float s0 = 0.f, s1 = 0.f, q0 = 0.f, q1 = 0.f;
#pragma unroll
        for (int m = 0; m < 2; m++) {
#pragma unroll
            for (int h = 0; h < 2; h++) {
                if (valid[m][h]) {
                    float v0 = acc[m][n][h * 2 + 0] + b0;
                    float v1 = acc[m][n][h * 2 + 1] + b1;
                    int row = rowBase + warpM * 32 + m * 16 + h * 8 + gid;
                    float2 st; st.x = v0; st.y = v1;
                    *reinterpret_cast<float2*>(out + (size_t)row * D + col) = st;
                    if (STATS) { s0 += v0; q0 += v0 * v0; s1 += v1; q1 += v1 * v1; }
                }
            }
        }
        if (STATS) {
#pragma unroll
            for (int sh = 4; sh <= 16; sh <<= 1) {
                s0 += __shfl_xor_sync(0xFFFFFFFFu, s0, sh);
                s1 += __shfl_xor_sync(0xFFFFFFFFu, s1, sh);
                q0 += __shfl_xor_sync(0xFFFFFFFFu, q0, sh);
                q1 += __shfl_xor_sync(0xFFFFFFFFu, q1, sh);
            }
            if (gid == 0) {
                sumS[warpM * 128 + col]     = s0;
                sumS[warpM * 128 + col + 1] = s1;
                sqS[warpM * 128 + col]      = q0;
                sqS[warpM * 128 + col + 1]  = q1;
            }
        }
    }

    if (STATS) {
        __syncthreads();
        if (tid < D) {
            float s = sumS[tid] + sumS[128 + tid] + sumS[256 + tid] + sumS[384 + tid];
            float q = sqS[tid] + sqS[128 + tid] + sqS[256 + tid] + sqS[384 + tid];
            atomicAdd(&g_stats[tid], s);
            atomicAdd(&g_stats[D + tid], q);
        }
    }
}

// ---------------- GraphNorm finalize (+ reset stats) ----------------
__global__ void finalize_kernel(const float* __restrict__ w,
                                const float* __restrict__ b,
                                const float* __restrict__ a)
{
    int j = threadIdx.x;
    const float invN = 1.0f / (float)NN;
    float mean = g_stats[j] * invN;
    float ex2  = g_stats[D + j] * invN;
    float aj = a[j];
    float var = ex2 - (2.0f * aj - aj * aj) * mean * mean;
    g_np[j]         = aj * mean;
    g_np[D + j]     = w[j] * rsqrtf(var + EPSV);
    g_np[2 * D + j] = b[j];
    g_stats[j] = 0.f;
    g_stats[D + j] = 0.f;
}

// ---------------- final: norm2 + relu + residual + bres -> out ----------------
__global__ void final_kernel(const float* __restrict__ h, float* __restrict__ o,
                             const float* __restrict__ bres)
{
    int idx = blockIdx.x * blockDim.x + threadIdx.x;
    if (idx >= NN * (D / 4)) return;
    int col = (idx & 31) * 4;
    float4 v = reinterpret_cast<const float4*>(h)[idx];
    float4 xr = reinterpret_cast<const float4*>(g_xres)[idx];
    float4 r;
    r.x = fmaxf(g_np[D + col + 0] * (v.x - g_np[col + 0]) + g_np[2 * D + col + 0], 0.f)
          + xr.x + __ldg(bres + col + 0);
    r.y = fmaxf(g_np[D + col + 1] * (v.y - g_np[col + 1]) + g_np[2 * D + col + 1], 0.f)
          + xr.y + __ldg(bres + col + 1);
    r.z = fmaxf(g_np[D + col + 2] * (v.z - g_np[col + 2]) + g_np[2 * D + col + 2], 0.f)
          + xr.z + __ldg(bres + col + 2);
    r.w = fmaxf(g_np[D + col + 3] * (v.w - g_np[col + 3]) + g_np[2 * D + col + 3], 0.f)
          + xr.w + __ldg(bres + col + 3);
    reinterpret_cast<float4*>(o)[idx] = r;
}

// ---------------- launch (single stream, serial — R10 ordering) ----------------
extern "C" void kernel_launch(void* const* d_in, const int* in_sizes, int n_in,
                              void* d_out, int out_size)
{
    const float* x    = (const float*)d_in[0];
    const int*   ei   = (const int*)d_in[1];
    const float* Wl1  = (const float*)d_in[2];
    const float* bl1  = (const float*)d_in[3];
    const float* Wr1  = (const float*)d_in[4];
    const float* Wl2  = (const float*)d_in[5];
    const float* bl2  = (const float*)d_in[6];
    const float* Wr2  = (const float*)d_in[7];
    const float* g1w  = (const float*)d_in[8];
    const float* g1b  = (const float*)d_in[9];
    const float* g1a  = (const float*)d_in[10];
    const float* g2w  = (const float*)d_in[11];
    const float* g2b  = (const float*)d_in[12];
    const float* g2a  = (const float*)d_in[13];
    const float* Wres = (const float*)d_in[14];
    const float* bres = (const float*)d_in[15];
    float* out = (float*)d_out;

    float *p_s, *p_hp, *p_xres, *p_Wc1, *p_Wc2, *p_Wrt;
    cudaGetSymbolAddress((void**)&p_s,    g_s);
    cudaGetSymbolAddress((void**)&p_hp,   g_hp);
    cudaGetSymbolAddress((void**)&p_xres, g_xres);
    cudaGetSymbolAddress((void**)&p_Wc1,  g_Wc1);
    cudaGetSymbolAddress((void**)&p_Wc2,  g_Wc2);
    cudaGetSymbolAddress((void**)&p_Wrt,  g_Wrt);

    const int SMEM = (4 * BUFF + 3 * D) * (int)sizeof(float);  // 75264
    static int attrDone = 0;
    if (!attrDone) {
        cudaFuncSetAttribute((const void*)gemm_mma<8, true, true, false>,
                             cudaFuncAttributeMaxDynamicSharedMemorySize, SMEM);
        cudaFuncSetAttribute((const void*)gemm_mma<8, true, true, true>,
                             cudaFuncAttributeMaxDynamicSharedMemorySize, SMEM);
        cudaFuncSetAttribute((const void*)gemm_mma<4, false, false, false>,
                             cudaFuncAttributeMaxDynamicSharedMemorySize, SMEM);
        attrDone = 1;
    }

    const int gemmBlocks = (NN + 127) / 128;          // 391
    const int gathBlocks = (NN + 7) / 8;              // 6250
    const int quadBlocks = (NE / 4 + 255) / 256;      // 782
    const int finBlocks  = (NN * (D / 4) + 255) / 256;

    // ---- prep + CSR build (parallel scan; reused by both layers) ----
    prep_w<<<(128 * 256 + 128 * 128 + 255) / 256, 256>>>(Wl1, Wr1, Wl2, Wr2, Wres);
    zero_kernel<<<(NN + 255) / 256, 256>>>();
    count_kernel<<<quadBlocks, 256>>>(ei);
    bsum_kernel<<<NBLK, 256>>>();
    bscan_kernel<<<1, 256>>>();
    rowptr_kernel<<<NBLK, 256>>>();
    fill_kernel<<<quadBlocks, 256>>>(ei);

    // ---- layer 1 ----
    gather_kernel<false><<<gathBlocks, 256>>>(x);
    gemm_mma<8, true, true, false><<<gemmBlocks, 256, SMEM>>>(p_s, x, p_Wc1, bl1, p_hp);
    gemm_mma<4, false, false, false><<<gemmBlocks, 256, SMEM>>>(x, x, p_Wrt, nullptr, p_xres);
    finalize_kernel<<<1, D>>>(g1w, g1b, g1a);

    // ---- layer 2 (h1 never materialized) ----
    gather_kernel<true><<<gathBlocks, 256>>>(p_hp);
    gemm_mma<8, true, true, true><<<gemmBlocks, 256, SMEM>>>(p_s, p_hp, p_Wc2, bl2, p_hp);
    finalize_kernel<<<1, D>>>(g2w, g2b, g2a);
    final_kernel<<<finBlocks, 256>>>(p_hp, out, bres);
}

// round 15
// speedup vs baseline: 1.0622x; 1.0622x over previous
#include <cuda_runtime.h>
#include <cstdint>

#define NN 50000
#define NE 800000
#define D  128
#define EPSV 1e-5f
#define NBLK 196   // ceil(NN/256)

// ---------------- scratch ----------------
__device__ float g_s[(size_t)NN * D];      // aggregated (mean) features
__device__ float g_hp[(size_t)NN * D];     // pre-norm GEMM output
__device__ float g_xres[(size_t)NN * D];   // x @ Wres^T
__device__ float g_stats[2 * D];
__device__ float g_np[3 * D];              // a*mean | w*rsqrt(var+eps) | b
__device__ int   g_icnt[NN];
__device__ int   g_rowptr[NN + 1];
__device__ int   g_fill[NN];
__device__ int   g_adj[NE];
__device__ int   g_bsum[NBLK];
__device__ int   g_boff[NBLK];
__device__ float g_Wc1[256 * 128];         // [n][k] tf32-rounded concat [Wl1|Wr1]
__device__ float g_Wc2[256 * 128];
__device__ float g_Wrt[128 * 128];         // [n][k] tf32-rounded Wres

// ---------------- tf32 helpers ----------------
__device__ __forceinline__ uint32_t f2tf32(float f) {
    uint32_t r;
    asm("cvt.rna.tf32.f32 %0, %1;" : "=r"(r) : "f"(f));
    return r;
}
__device__ __forceinline__ void mma_tf32(float* d, const uint32_t* a,
                                         uint32_t b0, uint32_t b1) {
    asm volatile(
        "mma.sync.aligned.m16n8k8.row.col.f32.tf32.tf32.f32 "
        "{%0,%1,%2,%3}, {%4,%5,%6,%7}, {%8,%9}, {%0,%1,%2,%3};"
        : "+f"(d[0]), "+f"(d[1]), "+f"(d[2]), "+f"(d[3])
        : "r"(a[0]), "r"(a[1]), "r"(a[2]), "r"(a[3]), "r"(b0), "r"(b1));
}
__device__ __forceinline__ uint32_t smem_u32(const void* p) {
    uint32_t a;
    asm("{ .reg .u64 t; cvta.to.shared.u64 t, %1; cvt.u32.u64 %0, t; }" : "=r"(a) : "l"(p));
    return a;
}
__device__ __forceinline__ void cp16(uint32_t dst, const void* src) {
    asm volatile("cp.async.cg.shared.global [%0], [%1], 16;" :: "r"(dst), "l"(src));
}
__device__ __forceinline__ void cp16z(uint32_t dst, const void* src, int sz) {
    asm volatile("cp.async.cg.shared.global [%0], [%1], 16, %2;"
                 :: "r"(dst), "l"(src), "r"(sz));
}

// ---------------- weight pre-conversion (tf32 round, concat layout) ----------
__global__ void prep_w(const float* __restrict__ Wl1, const float* __restrict__ Wr1,
                       const float* __restrict__ Wl2, const float* __restrict__ Wr2,
                       const float* __restrict__ Wres)
{
    int idx = blockIdx.x * blockDim.x + threadIdx.x;
    if (idx < 128 * 256) {
        int n = idx >> 8, k = idx & 255;
        float v1 = (k < D) ? Wl1[n * D + k] : Wr1[n * D + (k - D)];
        float v2 = (k < D) ? Wl2[n * D + k] : Wr2[n * D + (k - D)];
        g_Wc1[idx] = __uint_as_float(f2tf32(v1));
        g_Wc2[idx] = __uint_as_float(f2tf32(v2));
    } else if (idx < 128 * 256 + 128 * 128) {
        int t = idx - 128 * 256;
        g_Wrt[t] = __uint_as_float(f2tf32(Wres[t]));
    }
}

// ---------------- small zero (counters + stats) ----------------
__global__ void zero_kernel()
{
    int idx = blockIdx.x * blockDim.x + threadIdx.x;
    if (idx < NN) g_icnt[idx] = 0;
    if (idx < 2 * D) g_stats[idx] = 0.f;
}

// ---------------- CSR build (vectorized int4 edge reads) ----------------
__global__ void count_kernel(const int* __restrict__ ei)
{
    int q = blockIdx.x * blockDim.x + threadIdx.x;   // quad index
    if (q >= NE / 4) return;
    int4 d4 = __ldg(reinterpret_cast<const int4*>(ei + NE) + q);
    if ((unsigned)d4.x < NN) atomicAdd(&g_icnt[d4.x], 1);
    if ((unsigned)d4.y < NN) atomicAdd(&g_icnt[d4.y], 1);
    if ((unsigned)d4.z < NN) atomicAdd(&g_icnt[d4.z], 1);
    if ((unsigned)d4.w < NN) atomicAdd(&g_icnt[d4.w], 1);
}

__global__ void bsum_kernel()
{
    __shared__ int sh[256];
    int t = threadIdx.x;
    int i = blockIdx.x * 256 + t;
    int v = (i < NN) ? g_icnt[i] : 0;
    sh[t] = v;
    __syncthreads();
    for (int off = 128; off > 0; off >>= 1) {
        if (t < off) sh[t] += sh[t + off];
        __syncthreads();
    }
    if (t == 0) g_bsum[blockIdx.x] = sh[0];
}

__global__ void bscan_kernel()
{
    __shared__ int sh[256];
    int t = threadIdx.x;
    int v = (t < NBLK) ? g_bsum[t] : 0;
    sh[t] = v;
    __syncthreads();
#pragma unroll
    for (int off = 1; off < 256; off <<= 1) {
        int u = (t >= off) ? sh[t - off] : 0;
        __syncthreads();
        sh[t] += u;
        __syncthreads();
    }
    if (t < NBLK) g_boff[t] = sh[t] - v;   // exclusive
}

__global__ void rowptr_kernel()
{
    __shared__ int sh[256];
    int t = threadIdx.x;
    int i = blockIdx.x * 256 + t;
    int v = (i < NN) ? g_icnt[i] : 0;
    sh[t] = v;
    __syncthreads();
#pragma unroll
    for (int off = 1; off < 256; off <<= 1) {
        int u = (t >= off) ? sh[t - off] : 0;
        __syncthreads();
        sh[t] += u;
        __syncthreads();
    }
    if (i < NN) {
        int ex = g_boff[blockIdx.x] + sh[t] - v;
        g_rowptr[i] = ex;
        g_fill[i] = ex;
        if (i == NN - 1) g_rowptr[NN] = ex + v;
    }
}

__global__ void fill_kernel(const int* __restrict__ ei)
{
    int q = blockIdx.x * blockDim.x + threadIdx.x;
    if (q >= NE / 4) return;
    int4 s4 = __ldg(reinterpret_cast<const int4*>(ei) + q);
    int4 d4 = __ldg(reinterpret_cast<const int4*>(ei + NE) + q);
    if ((unsigned)s4.x < NN && (unsigned)d4.x < NN) g_adj[atomicAdd(&g_fill[d4.x], 1)] = s4.x;
    if ((unsigned)s4.y < NN && (unsigned)d4.y < NN) g_adj[atomicAdd(&g_fill[d4.y], 1)] = s4.y;
    if ((unsigned)s4.z < NN && (unsigned)d4.z < NN) g_adj[atomicAdd(&g_fill[d4.z], 1)] = s4.z;
    if ((unsigned)s4.w < NN && (unsigned)d4.w < NN) g_adj[atomicAdd(&g_fill[d4.w], 1)] = s4.w;
}

// ---------------- CSR gather (mean aggregate); NORM applies graphnorm+relu ----
template <bool NORM>
__global__ void gather_kernel(const float* __restrict__ src)
{
    int w = (blockIdx.x * blockDim.x + threadIdx.x) >> 5;
    int lane = threadIdx.x & 31;
    if (w >= NN) return;
    int beg = g_rowptr[w];
    int end = g_rowptr[w + 1];
    float4 nm, nw, nb;
    if (NORM) {
        nm = __ldg(reinterpret_cast<const float4*>(g_np) + lane);
        nw = __ldg(reinterpret_cast<const float4*>(g_np + D) + lane);
        nb = __ldg(reinterpret_cast<const float4*>(g_np + 2 * D) + lane);
    }
    float4 acc = make_float4(0.f, 0.f, 0.f, 0.f);
#pragma unroll 4
    for (int j = beg; j < end; j++) {
        int s = __ldg(g_adj + j);
        float4 v = __ldg(reinterpret_cast<const float4*>(src + (size_t)s * D) + lane);
        if (NORM) {
            v.x = fmaxf(nw.x * (v.x - nm.x) + nb.x, 0.f);
            v.y = fmaxf(nw.y * (v.y - nm.y) + nb.y, 0.f);
            v.z = fmaxf(nw.z * (v.z - nm.z) + nb.z, 0.f);
            v.w = fmaxf(nw.w * (v.w - nm.w) + nb.w, 0.f);
        }
        acc.x += v.x; acc.y += v.y; acc.z += v.z; acc.w += v.w;
    }
    float inv = 1.0f / fmaxf((float)(end - beg), 1.0f);
    acc.x *= inv; acc.y *= inv; acc.z *= inv; acc.w *= inv;
    reinterpret_cast<float4*>(g_s + (size_t)w * D)[lane] = acc;
}

// ---------------- mma.sync tf32 GEMM (R10 inner loop — no k-permutation) -------
// out[NN,128] = [A0 | normA1?(A1)] @ Wt^T (+bias); Wt pre-converted tf32 [n][KS]
#define KP 36
#define BUFF (128 * KP)

template <int KC, bool CONCAT, bool STATS, bool NORMA1>
__global__ __launch_bounds__(256, 2)
void gemm_mma(const float* __restrict__ A0, const float* __restrict__ A1,
              const float* __restrict__ Wt,
              const float* __restrict__ bias, float* __restrict__ out)
{
    constexpr int KS = KC * 32;
    extern __shared__ float sm[];
    float* As  = sm;                 // [2][128][KP]
    float* Bs  = sm + 2 * BUFF;      // [2][128][KP]
    float* npS = sm + 4 * BUFF;      // [384]
    float* sumS = sm;                // stats scratch (reuse As after compute)
    float* sqS  = sm + 512;

    const uint32_t sA = smem_u32(As);
    const uint32_t sB = smem_u32(Bs);
    const int tid = threadIdx.x;
    const int wid = tid >> 5, lane = tid & 31;
    const int warpM = wid >> 1;
    const int warpN = wid & 1;
    const int gid = lane >> 2;
    const int tg  = lane & 3;
    const int rowBase = blockIdx.x * 128;

    if (NORMA1) {
        for (int i = tid; i < 3 * D; i += 256) npS[i] = g_np[i];
    }

    float acc[2][8][4];
#pragma unroll
    for (int m = 0; m < 2; m++)
#pragma unroll
        for (int n = 0; n < 8; n++)
#pragma unroll
            for (int q = 0; q < 4; q++) acc[m][n][q] = 0.f;

    auto issueChunk = [&](int kc, int buf) {
#pragma unroll
        for (int i = 0; i < 4; i++) {
            int f = tid + i * 256;
            int r = f >> 3;
            int kg = f & 7;
            int k = kc * 32 + kg * 4;
            uint32_t soff = (uint32_t)(buf * BUFF + r * KP + kg * 4) * 4u;
            int rg = rowBase + r;
            const float* gp;
            if (CONCAT && k >= D) gp = A1 + (size_t)rg * D + (k - D);
            else                  gp = A0 + (size_t)rg * D + k;
            int sz = 16;
            if (rg >= NN) { gp = A0; sz = 0; }
            cp16z(sA + soff, gp, sz);
            cp16(sB + soff, Wt + r * KS + k);
        }
        asm volatile("cp.async.commit_group;" ::: "memory");
    };

    issueChunk(0, 0);

#pragma unroll
    for (int kc = 0; kc < KC; kc++) {
        if (kc + 1 < KC) {
            issueChunk(kc + 1, (kc + 1) & 1);
            asm volatile("cp.async.wait_group 1;" ::: "memory");
        } else {
            asm volatile("cp.async.wait_group 0;" ::: "memory");
        }
        __syncthreads();

        const int buf = kc & 1;
        const float* ab = &As[buf * BUFF];
        const float* bb = &Bs[buf * BUFF];
        const bool isA1 = CONCAT && (kc >= 4);

#pragma unroll
        for (int ks = 0; ks < 4; ks++) {
            const int kb = ks * 8;
            float nm0 = 0.f, nw0 = 1.f, nb0 = 0.f, nm1 = 0.f, nw1 = 1.f, nb1 = 0.f;
            if (NORMA1 && isA1) {
                int c0 = (kc - 4) * 32 + kb + tg;
                int c1 = c0 + 4;
                nm0 = npS[c0]; nw0 = npS[D + c0]; nb0 = npS[2 * D + c0];
                nm1 = npS[c1]; nw1 = npS[D + c1]; nb1 = npS[2 * D + c1];
            }
            uint32_t a[2][4];
#pragma unroll
            for (int m = 0; m < 2; m++) {
                int r1 = warpM * 32 + m * 16 + gid;
                int r2 = r1 + 8;
                float v0 = ab[r1 * KP + kb + tg];
                float v1 = ab[r2 * KP + kb + tg];
                float v2 = ab[r1 * KP + kb + tg + 4];
                float v3 = ab[r2 * KP + kb + tg + 4];
                if (NORMA1 && isA1) {
                    v0 = fmaxf(nw0 * (v0 - nm0) + nb0, 0.f);
                    v1 = fmaxf(nw0 * (v1 - nm0) + nb0, 0.f);
                    v2 = fmaxf(nw1 * (v2 - nm1) + nb1, 0.f);
                    v3 = fmaxf(nw1 * (v3 - nm1) + nb1, 0.f);
                }
                a[m][0] = f2tf32(v0); a[m][1] = f2tf32(v1);
                a[m][2] = f2tf32(v2); a[m][3] = f2tf32(v3);
            }
#pragma unroll
            for (int n = 0; n < 8; n++) {
                int c = warpN * 64 + n * 8 + gid;
                uint32_t b0 = __float_as_uint(bb[c * KP + kb + tg]);      // pre-tf32
                uint32_t b1 = __float_as_uint(bb[c * KP + kb + tg + 4]);
                mma_tf32(acc[0][n], a[0], b0, b1);
                mma_tf32(acc[1][n], a[1], b0, b1);
            }
        }
        __syncthreads();
    }

    // ---- epilogue: bias + store + (stats) ----
    const bool hasBias = (bias != nullptr);
    bool valid[2][2];
#pragma unroll
    for (int m = 0; m < 2; m++)
#pragma unroll
        for (int h = 0; h < 2; h++)
            valid[m][h] = (rowBase + warpM * 32 + m * 16 + h * 8 + gid) < NN;

#pragma unroll
    for (int n = 0; n < 8; n++) {
        int col = warpN * 64 + n * 8 + tg * 2;
        float b0 = hasBias ? __ldg(bias + col) : 0.f;
        float b1 = hasBias ? __ldg(bias + col + 1) : 0.f;
        float s0 = 0.f, s1 = 0.f, q0 = 0.f, q1 = 0.f;
#pragma unroll
        for (int m = 0; m < 2; m++) {
#pragma unroll
            for (int h = 0; h < 2; h++) {
                if (valid[m][h]) {
                    float v0 = acc[m][n][h * 2 + 0] + b0;
                    float v1 = acc[m][n][h * 2 + 1] + b1;
                    int row = rowBase + warpM * 32 + m * 16 + h * 8 + gid;
                    float2 st; st.x = v0; st.y = v1;
                    *reinterpret_cast<float2*>(out + (size_t)row * D + col) = st;
                    if (STATS) { s0 += v0; q0 += v0 * v0; s1 += v1; q1 += v1 * v1; }
                }
            }
        }
        if (STATS) {
#pragma unroll
            for (int sh = 4; sh <= 16; sh <<= 1) {
                s0 += __shfl_xor_sync(0xFFFFFFFFu, s0, sh);
                s1 += __shfl_xor_sync(0xFFFFFFFFu, s1, sh);
                q0 += __shfl_xor_sync(0xFFFFFFFFu, q0, sh);
                q1 += __shfl_xor_sync(0xFFFFFFFFu, q1, sh);
            }
            if (gid == 0) {
                sumS[warpM * 128 + col]     = s0;
                sumS[warpM * 128 + col + 1] = s1;
                sqS[warpM * 128 + col]      = q0;
                sqS[warpM * 128 + col + 1]  = q1;
            }
        }
    }

    if (STATS) {
        __syncthreads();
        if (tid < D) {
            float s = sumS[tid] + sumS[128 + tid] + sumS[256 + tid] + sumS[384 + tid];
            float q = sqS[tid] + sqS[128 + tid] + sqS[256 + tid] + sqS[384 + tid];
            atomicAdd(&g_stats[tid], s);
            atomicAdd(&g_stats[D + tid], q);
        }
    }
}

// ---------------- GraphNorm finalize (+ reset stats) ----------------
__global__ void finalize_kernel(const float* __restrict__ w,
                                const float* __restrict__ b,
                                const float* __restrict__ a)
{
    int j = threadIdx.x;
    const float invN = 1.0f / (float)NN;
    float mean = g_stats[j] * invN;
    float ex2  = g_stats[D + j] * invN;
    float aj = a[j];
    float var = ex2 - (2.0f * aj - aj * aj) * mean * mean;
    g_np[j]         = aj * mean;
    g_np[D + j]     = w[j] * rsqrtf(var + EPSV);
    g_np[2 * D + j] = b[j];
    g_stats[j] = 0.f;
    g_stats[D + j] = 0.f;
}

// ---------------- final: norm2 + relu + residual + bres -> out ----------------
__global__ void final_kernel(const float* __restrict__ h, float* __restrict__ o,
                             const float* __restrict__ bres)
{
    int idx = blockIdx.x * blockDim.x + threadIdx.x;
    if (idx >= NN * (D / 4)) return;
    int col = (idx & 31) * 4;
    float4 v = reinterpret_cast<const float4*>(h)[idx];
    float4 xr = reinterpret_cast<const float4*>(g_xres)[idx];
    float4 r;
    r.x = fmaxf(g_np[D + col + 0] * (v.x - g_np[col + 0]) + g_np[2 * D + col + 0], 0.f)
          + xr.x + __ldg(bres + col + 0);
    r.y = fmaxf(g_np[D + col + 1] * (v.y - g_np[col + 1]) + g_np[2 * D + col + 1], 0.f)
          + xr.y + __ldg(bres + col + 1);
    r.z = fmaxf(g_np[D + col + 2] * (v.z - g_np[col + 2]) + g_np[2 * D + col + 2], 0.f)
          + xr.z + __ldg(bres + col + 2);
    r.w = fmaxf(g_np[D + col + 3] * (v.w - g_np[col + 3]) + g_np[2 * D + col + 3], 0.f)
          + xr.w + __ldg(bres + col + 3);
    reinterpret_cast<float4*>(o)[idx] = r;
}

// ---------------- launch (single stream, serial — R10 ordering) ----------------
extern "C" void kernel_launch(void* const* d_in, const int* in_sizes, int n_in,
                              void* d_out, int out_size)
{
    const float* x    = (const float*)d_in[0];
    const int*   ei   = (const int*)d_in[1];
    const float* Wl1  = (const float*)d_in[2];
    const float* bl1  = (const float*)d_in[3];
    const float* Wr1  = (const float*)d_in[4];
    const float* Wl2  = (const float*)d_in[5];
    const float* bl2  = (const float*)d_in[6];
    const float* Wr2  = (const float*)d_in[7];
    const float* g1w  = (const float*)d_in[8];
    const float* g1b  = (const float*)d_in[9];
    const float* g1a  = (const float*)d_in[10];
    const float* g2w  = (const float*)d_in[11];
    const float* g2b  = (const float*)d_in[12];
    const float* g2a  = (const float*)d_in[13];
    const float* Wres = (const float*)d_in[14];
    const float* bres = (const float*)d_in[15];
    float* out = (float*)d_out;

    float *p_s, *p_hp, *p_xres, *p_Wc1, *p_Wc2, *p_Wrt;
    cudaGetSymbolAddress((void**)&p_s,    g_s);
    cudaGetSymbolAddress((void**)&p_hp,   g_hp);
    cudaGetSymbolAddress((void**)&p_xres, g_xres);
    cudaGetSymbolAddress((void**)&p_Wc1,  g_Wc1);
    cudaGetSymbolAddress((void**)&p_Wc2,  g_Wc2);
    cudaGetSymbolAddress((void**)&p_Wrt,  g_Wrt);

    const int SMEM = (4 * BUFF + 3 * D) * (int)sizeof(float);  // 75264
    static int attrDone = 0;
    if (!attrDone) {
        cudaFuncSetAttribute((const void*)gemm_mma<8, true, true, false>,
                             cudaFuncAttributeMaxDynamicSharedMemorySize, SMEM);
        cudaFuncSetAttribute((const void*)gemm_mma<8, true, true, true>,
                             cudaFuncAttributeMaxDynamicSharedMemorySize, SMEM);
        cudaFuncSetAttribute((const void*)gemm_mma<4, false, false, false>,
                             cudaFuncAttributeMaxDynamicSharedMemorySize, SMEM);
        attrDone = 1;
    }

    const int gemmBlocks = (NN + 127) / 128;          // 391
    const int gathBlocks = (NN + 7) / 8;              // 6250
    const int quadBlocks = (NE / 4 + 255) / 256;      // 782
    const int finBlocks  = (NN * (D / 4) + 255) / 256;

    // ---- prep + CSR build (parallel scan; reused by both layers) ----
    prep_w<<<(128 * 256 + 128 * 128 + 255) / 256, 256>>>(Wl1, Wr1, Wl2, Wr2, Wres);
    zero_kernel<<<(NN + 255) / 256, 256>>>();
    count_kernel<<<quadBlocks, 256>>>(ei);
    bsum_kernel<<<NBLK, 256>>>();
    bscan_kernel<<<1, 256>>>();
    rowptr_kernel<<<NBLK, 256>>>();
    fill_kernel<<<quadBlocks, 256>>>(ei);

    // ---- layer 1 ----
    gather_kernel<false><<<gathBlocks, 256>>>(x);
    gemm_mma<8, true, true, false><<<gemmBlocks, 256, SMEM>>>(p_s, x, p_Wc1, bl1, p_hp);
    gemm_mma<4, false, false, false><<<gemmBlocks, 256, SMEM>>>(x, x, p_Wrt, nullptr, p_xres);
    finalize_kernel<<<1, D>>>(g1w, g1b, g1a);

    // ---- layer 2 (h1 never materialized) ----
    gather_kernel<true><<<gathBlocks, 256>>>(p_hp);
    gemm_mma<8, true, true, true><<<gemmBlocks, 256, SMEM>>>(p_s, p_hp, p_Wc2, bl2, p_hp);
    finalize_kernel<<<1, D>>>(g2w, g2b, g2a);
    final_kernel<<<finBlocks, 256>>>(p_hp, out, bres);
}